// round 8
// baseline (speedup 1.0000x reference)
#include <cuda_runtime.h>

#define Bn 8
#define Cn 64
#define Hn 64
#define Wn 64

typedef unsigned long long ull;

__device__ __forceinline__ ull pack2(float lo, float hi) {
    ull r; asm("mov.b64 %0, {%1, %2};" : "=l"(r) : "f"(lo), "f"(hi)); return r;
}
__device__ __forceinline__ void unpack2(ull v, float& lo, float& hi) {
    asm("mov.b64 {%0, %1}, %2;" : "=f"(lo), "=f"(hi) : "l"(v));
}
__device__ __forceinline__ ull ffma2(ull a, ull b, ull c) {
    ull d; asm("fma.rn.f32x2 %0, %1, %2, %3;" : "=l"(d) : "l"(a), "l"(b), "l"(c)); return d;
}

__device__ float g_f1[Bn*64*Hn*Wn];    // conv1 out [b][c][h][w]
__device__ float g_f2t[Bn*32*Wn*Hn];   // conv2 out transposed [b][c][w][h]

// ---------------------------------------------------------------------------
// conv1: 3x3 64->64, zero pad, bias+PReLU.
// Block = 2 h-rows x 32 co, 128 thr. Warp = full row, 8 co, 2 rows.
// Lane = pixel pair. Pixel LDS.64 lane-strided; weight LDS.128 broadcast.
// Grid (32 rowpairs, 2 co-groups, 8 batch) = 512 blocks.
// ---------------------------------------------------------------------------
__global__ __launch_bounds__(128, 4) void conv1_kernel(
    const float* __restrict__ x, const float* __restrict__ wgt,
    const float* __restrict__ bias, const float* __restrict__ alpha)
{
    const int rp  = blockIdx.x;          // rows 2rp, 2rp+1
    const int cog = blockIdx.y;          // co base 32*cog
    const int b   = blockIdx.z;
    const int tid  = threadIdx.x;
    const int lane = tid & 31;           // pixel pair (2l, 2l+1)
    const int wrp  = tid >> 5;
    const int cob  = wrp * 8;            // co offset within 32-group

    __shared__ __align__(16) float sA[4][4][64];  // [ci][r][w] aligned pairs
    __shared__ __align__(16) float sB[4][4][68];  // [ci][r][2p..]=(x[2p-1],x[2p])
    __shared__ __align__(16) ull   sW[4][9][32];  // [ci][k][co] dup pairs

    const int fi_ci = tid >> 5, fi_r = (tid >> 3) & 3, fi_seg = tid & 7;
    const int hh  = 2*rp - 1 + fi_r;
    const bool inh = (hh >= 0) && (hh < Hn);
    const int fw_co = tid & 31, fw_ci = tid >> 5;

    ull acc[8][2];
#pragma unroll
    for (int i = 0; i < 8; i++) { acc[i][0] = 0ull; acc[i][1] = 0ull; }

    for (int cb = 0; cb < 16; cb++) {
        {   // input fill: (ci, row, 8-col segment)
            float4 g0 = make_float4(0.f,0.f,0.f,0.f), g1 = g0;
            float xm1 = 0.f;
            if (inh) {
                const float* src = x + ((b*64 + cb*4 + fi_ci)*Hn + hh)*Wn + fi_seg*8;
                g0 = *(const float4*)src;
                g1 = *(const float4*)(src + 4);
                if (fi_seg > 0) xm1 = src[-1];
            }
            *(float4*)&sA[fi_ci][fi_r][fi_seg*8]     = g0;
            *(float4*)&sA[fi_ci][fi_r][fi_seg*8 + 4] = g1;
            *(float4*)&sB[fi_ci][fi_r][fi_seg*8]     = make_float4(xm1, g0.x, g0.y, g0.z);
            *(float4*)&sB[fi_ci][fi_r][fi_seg*8 + 4] = make_float4(g0.w, g1.x, g1.y, g1.z);
            if (fi_seg == 7) { sB[fi_ci][fi_r][64] = g1.w; sB[fi_ci][fi_r][65] = 0.f; }
        }
        {   // weight fill: thread = (co32, ci4), 9 k each
            const float* wp = wgt + ((cog*32 + fw_co)*64 + cb*4 + fw_ci)*9;
#pragma unroll
            for (int k = 0; k < 9; k++) {
                float v = wp[k];
                sW[fw_ci][k][fw_co] = pack2(v, v);
            }
        }
        __syncthreads();

#pragma unroll
        for (int ci = 0; ci < 4; ci++) {
            ull Ar[2], Bl[2], Bh[2];
#pragma unroll
            for (int r = 0; r < 2; r++) {
                Ar[r] = *(const ull*)&sA[ci][r][2*lane];
                Bl[r] = *(const ull*)&sB[ci][r][2*lane];
                Bh[r] = *(const ull*)&sB[ci][r][2*lane + 2];
            }
#pragma unroll
            for (int ky = 0; ky < 3; ky++) {
                if (ky > 0) {   // roll rows: out r uses input row r+ky
                    Ar[0] = Ar[1]; Bl[0] = Bl[1]; Bh[0] = Bh[1];
                    Ar[1] = *(const ull*)&sA[ci][ky+1][2*lane];
                    Bl[1] = *(const ull*)&sB[ci][ky+1][2*lane];
                    Bh[1] = *(const ull*)&sB[ci][ky+1][2*lane + 2];
                }
#pragma unroll
                for (int kx = 0; kx < 3; kx++) {
                    const ull* wp2 = &sW[ci][ky*3 + kx][cob];   // warp-uniform
                    ulonglong2 w01 = *(const ulonglong2*)(wp2);
                    ulonglong2 w23 = *(const ulonglong2*)(wp2 + 2);
                    ulonglong2 w45 = *(const ulonglong2*)(wp2 + 4);
                    ulonglong2 w67 = *(const ulonglong2*)(wp2 + 6);
                    ull wv[8] = {w01.x,w01.y,w23.x,w23.y,w45.x,w45.y,w67.x,w67.y};
#pragma unroll
                    for (int co = 0; co < 8; co++)
#pragma unroll
                        for (int r = 0; r < 2; r++) {
                            ull px = (kx == 0) ? Bl[r] : (kx == 1) ? Ar[r] : Bh[r];
                            acc[co][r] = ffma2(wv[co], px, acc[co][r]);
                        }
                }
            }
        }
        __syncthreads();
    }

#pragma unroll
    for (int co = 0; co < 8; co++) {
        const int cg_ = cog*32 + cob + co;
        const float bv = bias[cg_], av = alpha[cg_];
#pragma unroll
        for (int r = 0; r < 2; r++) {
            float lo, hi; unpack2(acc[co][r], lo, hi);
            lo += bv; hi += bv;
            lo = lo > 0.f ? lo : av*lo;
            hi = hi > 0.f ? hi : av*hi;
            *(float2*)&g_f1[((b*64 + cg_)*Hn + 2*rp + r)*Wn + 2*lane] = make_float2(lo, hi);
        }
    }
}

// ---------------------------------------------------------------------------
// conv2: 3x3 64->32, zero pad, bias+PReLU, transposed out [b][c][w][h].
// Same structure: warp = row, 8 co, 2 rows. Grid (32, 8) = 256 blocks.
// ---------------------------------------------------------------------------
__global__ __launch_bounds__(128, 4) void conv2_kernel(
    const float* __restrict__ wgt, const float* __restrict__ bias,
    const float* __restrict__ alpha)
{
    const int rp = blockIdx.x;
    const int b  = blockIdx.y;
    const int tid  = threadIdx.x;
    const int lane = tid & 31;
    const int wrp  = tid >> 5;
    const int cob  = wrp * 8;

    __shared__ __align__(16) float sA[4][4][64];
    __shared__ __align__(16) float sB[4][4][68];
    __shared__ __align__(16) ull   sW[4][9][32];

    const int fi_ci = tid >> 5, fi_r = (tid >> 3) & 3, fi_seg = tid & 7;
    const int hh  = 2*rp - 1 + fi_r;
    const bool inh = (hh >= 0) && (hh < Hn);
    const int fw_co = tid & 31, fw_ci = tid >> 5;

    ull acc[8][2];
#pragma unroll
    for (int i = 0; i < 8; i++) { acc[i][0] = 0ull; acc[i][1] = 0ull; }

    for (int cb = 0; cb < 16; cb++) {
        {
            float4 g0 = make_float4(0.f,0.f,0.f,0.f), g1 = g0;
            float xm1 = 0.f;
            if (inh) {
                const float* src = g_f1 + ((b*64 + cb*4 + fi_ci)*Hn + hh)*Wn + fi_seg*8;
                g0 = *(const float4*)src;
                g1 = *(const float4*)(src + 4);
                if (fi_seg > 0) xm1 = src[-1];
            }
            *(float4*)&sA[fi_ci][fi_r][fi_seg*8]     = g0;
            *(float4*)&sA[fi_ci][fi_r][fi_seg*8 + 4] = g1;
            *(float4*)&sB[fi_ci][fi_r][fi_seg*8]     = make_float4(xm1, g0.x, g0.y, g0.z);
            *(float4*)&sB[fi_ci][fi_r][fi_seg*8 + 4] = make_float4(g0.w, g1.x, g1.y, g1.z);
            if (fi_seg == 7) { sB[fi_ci][fi_r][64] = g1.w; sB[fi_ci][fi_r][65] = 0.f; }
        }
        {   // 32 co x 4 ci = 128 threads, 9 k each
            const float* wp = wgt + (fw_co*64 + cb*4 + fw_ci)*9;
#pragma unroll
            for (int k = 0; k < 9; k++) {
                float v = wp[k];
                sW[fw_ci][k][fw_co] = pack2(v, v);
            }
        }
        __syncthreads();

#pragma unroll
        for (int ci = 0; ci < 4; ci++) {
            ull Ar[2], Bl[2], Bh[2];
#pragma unroll
            for (int r = 0; r < 2; r++) {
                Ar[r] = *(const ull*)&sA[ci][r][2*lane];
                Bl[r] = *(const ull*)&sB[ci][r][2*lane];
                Bh[r] = *(const ull*)&sB[ci][r][2*lane + 2];
            }
#pragma unroll
            for (int ky = 0; ky < 3; ky++) {
                if (ky > 0) {
                    Ar[0] = Ar[1]; Bl[0] = Bl[1]; Bh[0] = Bh[1];
                    Ar[1] = *(const ull*)&sA[ci][ky+1][2*lane];
                    Bl[1] = *(const ull*)&sB[ci][ky+1][2*lane];
                    Bh[1] = *(const ull*)&sB[ci][ky+1][2*lane + 2];
                }
#pragma unroll
                for (int kx = 0; kx < 3; kx++) {
                    const ull* wp2 = &sW[ci][ky*3 + kx][cob];
                    ulonglong2 w01 = *(const ulonglong2*)(wp2);
                    ulonglong2 w23 = *(const ulonglong2*)(wp2 + 2);
                    ulonglong2 w45 = *(const ulonglong2*)(wp2 + 4);
                    ulonglong2 w67 = *(const ulonglong2*)(wp2 + 6);
                    ull wv[8] = {w01.x,w01.y,w23.x,w23.y,w45.x,w45.y,w67.x,w67.y};
#pragma unroll
                    for (int co = 0; co < 8; co++)
#pragma unroll
                        for (int r = 0; r < 2; r++) {
                            ull px = (kx == 0) ? Bl[r] : (kx == 1) ? Ar[r] : Bh[r];
                            acc[co][r] = ffma2(wv[co], px, acc[co][r]);
                        }
                }
            }
        }
        __syncthreads();
    }

#pragma unroll
    for (int co = 0; co < 8; co++) {
        const int cg_ = cob + co;
        const float bv = bias[cg_], av = alpha[cg_];
#pragma unroll
        for (int r = 0; r < 2; r++) {
            float lo, hi; unpack2(acc[co][r], lo, hi);
            lo += bv; hi += bv;
            lo = lo > 0.f ? lo : av*lo;
            hi = hi > 0.f ? hi : av*hi;
            const int h = 2*rp + r;
            g_f2t[((b*32 + cg_)*Wn + 2*lane    )*Hn + h] = lo;
            g_f2t[((b*32 + cg_)*Wn + 2*lane + 1)*Hn + h] = hi;
        }
    }
}

// ---------------------------------------------------------------------------
// Fused: 1x1 conv (K=32) + softmax(9) + upsample. 128 thr, 8192 blocks.
// Dup-pair weight smem [cg][ci][10]: 5 loads/ci, 4 unique addrs/warp, no packs.
// Thread = (c_l, pq, pg): 9 logits x 8 h-pixels. out[b][c][2w+q][2h+p].
// ---------------------------------------------------------------------------
__global__ __launch_bounds__(128, 3) void fused_kernel(
    const float* __restrict__ xlow, const float* __restrict__ kw,
    const float* __restrict__ kb, float* __restrict__ out)
{
    const int cchunk = blockIdx.x;
    const int w      = blockIdx.y;
    const int b      = blockIdx.z;
    const int tid = threadIdx.x;
    const int pg  = tid & 7;
    const int pq  = (tid >> 3) & 3;
    const int c_l = tid >> 5;
    const int cg  = c_l*4 + pq;

    __shared__ __align__(16) ull   sWd[16*32*10];   // [cg][ci][k pad10] dup pairs
    __shared__ __align__(16) float sf2[32*64];      // [ci][h]
    __shared__ __align__(16) float sx[4][3][68];    // edge-clamped x_low patch
    __shared__ float sbias[144];

    for (int idx = tid; idx < 32*64; idx += 128)
        sf2[idx] = g_f2t[((b*32 + (idx >> 6))*Wn + w)*Hn + (idx & 63)];
    for (int idx = tid; idx < 144*32; idx += 128) {
        const int r = idx >> 5, ci = idx & 31;
        const float v = kw[(cchunk*144 + r)*32 + ci];
        const int cl2 = r / 36;
        const int rem = r - cl2*36;
        const int k   = rem >> 2;
        const int cg2 = cl2*4 + (rem & 3);
        sWd[(cg2*32 + ci)*10 + k] = pack2(v, v);
    }
    for (int idx = tid; idx < 144; idx += 128) sbias[idx] = kb[cchunk*144 + idx];
    for (int idx = tid; idx < 4*3*66; idx += 128) {
        int cl = idx / 198;
        int dx = (idx % 198) / 66;
        int hh = idx % 66;
        int hr = min(max(hh - 1, 0), Hn - 1);
        int wc = min(max(w + dx - 1, 0), Wn - 1);
        sx[cl][dx][hh] = xlow[((b*Cn + cchunk*4 + cl)*Hn + hr)*Wn + wc];
    }
    __syncthreads();

    ull m[9][4];
#pragma unroll
    for (int k = 0; k < 9; k++)
#pragma unroll
        for (int j = 0; j < 4; j++) m[k][j] = 0ull;

    const ull* wrow = &sWd[cg*320];

#pragma unroll 4
    for (int ci = 0; ci < 32; ci++) {
        ulonglong2 p01 = *(const ulonglong2*)&sf2[ci*64 + pg*8];
        ulonglong2 p23 = *(const ulonglong2*)&sf2[ci*64 + pg*8 + 4];
        ull P[4] = {p01.x, p01.y, p23.x, p23.y};
        const ull* wp = wrow + ci*10;
        ulonglong2 w01 = *(const ulonglong2*)(wp);
        ulonglong2 w23 = *(const ulonglong2*)(wp + 2);
        ulonglong2 w45 = *(const ulonglong2*)(wp + 4);
        ulonglong2 w67 = *(const ulonglong2*)(wp + 6);
        ull W[9] = {w01.x, w01.y, w23.x, w23.y, w45.x, w45.y, w67.x, w67.y, wp[8]};
#pragma unroll
        for (int k = 0; k < 9; k++)
#pragma unroll
            for (int j = 0; j < 4; j++) m[k][j] = ffma2(W[k], P[j], m[k][j]);
    }

    const int rowb = c_l*36 + pq;
    float b9[9];
#pragma unroll
    for (int k = 0; k < 9; k++) b9[k] = sbias[rowb + k*4];

    float nbd[3][10];
#pragma unroll
    for (int dx = 0; dx < 3; dx++) {
        float4 q0 = *(const float4*)&sx[c_l][dx][pg*8];
        float4 q1 = *(const float4*)&sx[c_l][dx][pg*8 + 4];
        float2 q2 = *(const float2*)&sx[c_l][dx][pg*8 + 8];
        nbd[dx][0]=q0.x; nbd[dx][1]=q0.y; nbd[dx][2]=q0.z; nbd[dx][3]=q0.w;
        nbd[dx][4]=q1.x; nbd[dx][5]=q1.y; nbd[dx][6]=q1.z; nbd[dx][7]=q1.w;
        nbd[dx][8]=q2.x; nbd[dx][9]=q2.y;
    }

    const int c = cchunk*4 + c_l;
    const int p = pq >> 1, q = pq & 1;
    float* orow = &out[((b*Cn + c)*128 + (2*w + q))*128 + p];

#pragma unroll
    for (int jj = 0; jj < 4; jj++) {
        float lo[9], hi[9];
#pragma unroll
        for (int k = 0; k < 9; k++) unpack2(m[k][jj], lo[k], hi[k]);
#pragma unroll
        for (int e = 0; e < 2; e++) {
            const int j = 2*jj + e;
            const float* lv = e ? hi : lo;
            float se = 0.f, sv = 0.f;
#pragma unroll
            for (int k = 0; k < 9; k++) {
                float ex = __expf(lv[k] + b9[k]);   // logits tiny: no max-sub needed
                se += ex;
                sv = fmaf(ex, nbd[k % 3][j + k / 3], sv);
            }
            orow[2*(pg*8 + j)] = sv * __fdividef(1.f, se);
        }
    }
}

extern "C" void kernel_launch(void* const* d_in, const int* in_sizes, int n_in,
                              void* d_out, int out_size)
{
    const float* x_low = (const float*)d_in[0];
    const float* ctx   = (const float*)d_in[1];
    const float* c1_w  = (const float*)d_in[2];
    const float* c1_b  = (const float*)d_in[3];
    const float* p1_a  = (const float*)d_in[4];
    const float* c2_w  = (const float*)d_in[5];
    const float* c2_b  = (const float*)d_in[6];
    const float* p2_a  = (const float*)d_in[7];
    const float* kp_w  = (const float*)d_in[8];
    const float* kp_b  = (const float*)d_in[9];
    float* out = (float*)d_out;

    conv1_kernel<<<dim3(Hn/2, 2, Bn), 128>>>(ctx, c1_w, c1_b, p1_a);
    conv2_kernel<<<dim3(Hn/2, Bn), 128>>>(c2_w, c2_b, p2_a);
    fused_kernel<<<dim3(16, Wn, Bn), 128>>>(x_low, kp_w, kp_b, out);
}

// round 11
// speedup vs baseline: 1.2664x; 1.2664x over previous
#include <cuda_runtime.h>

#define Bn 8
#define Cn 64
#define Hn 64
#define Wn 64

typedef unsigned long long ull;

__device__ __forceinline__ ull pack2(float lo, float hi) {
    ull r; asm("mov.b64 %0, {%1, %2};" : "=l"(r) : "f"(lo), "f"(hi)); return r;
}
__device__ __forceinline__ void unpack2(ull v, float& lo, float& hi) {
    asm("mov.b64 {%0, %1}, %2;" : "=f"(lo), "=f"(hi) : "l"(v));
}
__device__ __forceinline__ ull ffma2(ull a, ull b, ull c) {
    ull d; asm("fma.rn.f32x2 %0, %1, %2, %3;" : "=l"(d) : "l"(a), "l"(b), "l"(c)); return d;
}
// (a.hi, b.lo)
__device__ __forceinline__ ull sp(ull a, ull b) {
    ull r;
    asm("{\n\t.reg .f32 al, ah, bl, bh;\n\t"
        "mov.b64 {al, ah}, %1;\n\t"
        "mov.b64 {bl, bh}, %2;\n\t"
        "mov.b64 %0, {ah, bl};\n\t}"
        : "=l"(r) : "l"(a), "l"(b));
    return r;
}
// (e, b.lo)
__device__ __forceinline__ ull spf(float e, ull b) {
    ull r;
    asm("{\n\t.reg .f32 bl, bh;\n\t"
        "mov.b64 {bl, bh}, %2;\n\t"
        "mov.b64 %0, {%1, bl};\n\t}"
        : "=l"(r) : "f"(e), "l"(b));
    return r;
}
// (a.hi, e)
__device__ __forceinline__ ull spl(ull a, float e) {
    ull r;
    asm("{\n\t.reg .f32 al, ah;\n\t"
        "mov.b64 {al, ah}, %1;\n\t"
        "mov.b64 %0, {ah, %2};\n\t}"
        : "=l"(r) : "l"(a), "f"(e));
    return r;
}

__device__ float g_f1[Bn*64*Hn*Wn];    // conv1 out [b][c][h][w]
__device__ float g_f2t[Bn*32*Wn*Hn];   // conv2 out transposed [b][c][w][h]

// Load a 16-px row segment as 8 aligned pairs + 9 shifted pairs.
__device__ __forceinline__ void load_row(ull* AP, ull* S, const float* rowp,
                                         int s16, bool notfirst, bool notlast)
{
    const float* rp = rowp + s16;
    ulonglong2 q0 = *(const ulonglong2*)(rp);
    ulonglong2 q1 = *(const ulonglong2*)(rp + 4);
    ulonglong2 q2 = *(const ulonglong2*)(rp + 8);
    ulonglong2 q3 = *(const ulonglong2*)(rp + 12);
    AP[0]=q0.x; AP[1]=q0.y; AP[2]=q1.x; AP[3]=q1.y;
    AP[4]=q2.x; AP[5]=q2.y; AP[6]=q3.x; AP[7]=q3.y;
    float eL = notfirst ? rp[-1] : 0.f;
    float eR = notlast  ? rp[16] : 0.f;
    S[0] = spf(eL, AP[0]);
#pragma unroll
    for (int j = 1; j < 8; j++) S[j] = sp(AP[j-1], AP[j]);
    S[8] = spl(AP[7], eR);
}

// acc[p] += W0*S[p] + W1*AP[p] + W2*S[p+1]
__device__ __forceinline__ void fma_row(ull* acc, const ull* AP, const ull* S,
                                        ull W0, ull W1, ull W2)
{
#pragma unroll
    for (int p = 0; p < 8; p++) {
        acc[p] = ffma2(W0, S[p],   acc[p]);
        acc[p] = ffma2(W1, AP[p],  acc[p]);
        acc[p] = ffma2(W2, S[p+1], acc[p]);
    }
}

// ---------------------------------------------------------------------------
// conv1: 3x3 64->64, zero pad, bias+PReLU. lane = co.
// Block 256 thr = 8 warps (coHalf x 4 px-segs). 2 output rows per block.
// Per warp-ci: 9 wf weights + 72 wf pixels vs 144 FFMA2.
// ---------------------------------------------------------------------------
__global__ __launch_bounds__(256, 2) void conv1_kernel(
    const float* __restrict__ x, const float* __restrict__ wgt,
    const float* __restrict__ bias, const float* __restrict__ alpha)
{
    const int h0 = blockIdx.x * 2, b = blockIdx.y;
    const int tid  = threadIdx.x;
    const int lane = tid & 31;
    const int ww   = tid >> 5;
    const int coH  = ww & 1;
    const int seg  = ww >> 1;            // 0..3
    const int co   = coH*32 + lane;
    const int s16  = seg * 16;
    const bool nf = (seg > 0), nl = (seg < 3);

    __shared__ __align__(16) float sIn[8][4][64];   // [ci][rr][w], rr = h0-1+rr
    __shared__ float sWt[8][9][64];                 // [ci][k][co]

    const int fw_co = tid >> 2, fw_ci0 = (tid & 3) * 2;

    ull acc[2][8];
#pragma unroll
    for (int r = 0; r < 2; r++)
#pragma unroll
        for (int p = 0; p < 8; p++) acc[r][p] = 0ull;

    for (int cb = 0; cb < 8; cb++) {
        // input fill: 512 float4, 2 per thread
#pragma unroll
        for (int t = 0; t < 2; t++) {
            const int i  = tid + t*256;
            const int ci = i >> 6, rr = (i >> 4) & 3, c4 = i & 15;
            const int hh = h0 - 1 + rr;
            float4 v = make_float4(0.f, 0.f, 0.f, 0.f);
            if (hh >= 0 && hh < Hn)
                v = *(const float4*)&x[((b*64 + cb*8 + ci)*Hn + hh)*Wn + c4*4];
            *(float4*)&sIn[ci][rr][c4*4] = v;
        }
        // weight fill: thread = (co64, 2-ci)
        {
            const float* wp = wgt + (fw_co*64 + cb*8 + fw_ci0)*9;
#pragma unroll
            for (int cc = 0; cc < 2; cc++)
#pragma unroll
                for (int k = 0; k < 9; k++)
                    sWt[fw_ci0 + cc][k][fw_co] = wp[cc*9 + k];
        }
        __syncthreads();

#pragma unroll 2
        for (int ci = 0; ci < 8; ci++) {
            ull A_AP[8], A_S[9], B_AP[8], B_S[9];
            load_row(A_AP, A_S, &sIn[ci][0][0], s16, nf, nl);
            load_row(B_AP, B_S, &sIn[ci][1][0], s16, nf, nl);
            const float* wr = &sWt[ci][0][co];
            {   // ky = 0: out0<-row0(A), out1<-row1(B)
                float v0 = wr[0], v1 = wr[64], v2 = wr[128];
                ull W0 = pack2(v0,v0), W1 = pack2(v1,v1), W2 = pack2(v2,v2);
                fma_row(acc[0], A_AP, A_S, W0, W1, W2);
                fma_row(acc[1], B_AP, B_S, W0, W1, W2);
            }
            load_row(A_AP, A_S, &sIn[ci][2][0], s16, nf, nl);
            {   // ky = 1: out0<-row1(B), out1<-row2(A)
                float v0 = wr[192], v1 = wr[256], v2 = wr[320];
                ull W0 = pack2(v0,v0), W1 = pack2(v1,v1), W2 = pack2(v2,v2);
                fma_row(acc[0], B_AP, B_S, W0, W1, W2);
                fma_row(acc[1], A_AP, A_S, W0, W1, W2);
            }
            load_row(B_AP, B_S, &sIn[ci][3][0], s16, nf, nl);
            {   // ky = 2: out0<-row2(A), out1<-row3(B)
                float v0 = wr[384], v1 = wr[448], v2 = wr[512];
                ull W0 = pack2(v0,v0), W1 = pack2(v1,v1), W2 = pack2(v2,v2);
                fma_row(acc[0], A_AP, A_S, W0, W1, W2);
                fma_row(acc[1], B_AP, B_S, W0, W1, W2);
            }
        }
        __syncthreads();
    }

    const float bv = bias[co], av = alpha[co];
#pragma unroll
    for (int r = 0; r < 2; r++) {
        float o[16];
#pragma unroll
        for (int p = 0; p < 8; p++) unpack2(acc[r][p], o[2*p], o[2*p+1]);
#pragma unroll
        for (int e = 0; e < 16; e++) {
            float v = o[e] + bv;
            o[e] = v > 0.f ? v : av*v;
        }
        float* op = &g_f1[((b*64 + co)*Hn + h0 + r)*Wn + s16];
#pragma unroll
        for (int q = 0; q < 4; q++)
            *(float4*)(op + 4*q) = make_float4(o[4*q], o[4*q+1], o[4*q+2], o[4*q+3]);
    }
}

// ---------------------------------------------------------------------------
// conv2: 3x3 64->32, zero pad, bias+PReLU, transposed out [b][c][w][h].
// lane = co (all 32). Block 256 thr = 8 warps (2 rowpairs x 4 segs), 4 rows.
// ---------------------------------------------------------------------------
__global__ __launch_bounds__(256, 2) void conv2_kernel(
    const float* __restrict__ wgt, const float* __restrict__ bias,
    const float* __restrict__ alpha)
{
    const int h0 = blockIdx.x * 4, b = blockIdx.y;
    const int tid  = threadIdx.x;
    const int lane = tid & 31;        // co
    const int ww   = tid >> 5;
    const int rp2  = ww >> 2;         // rowpair 0..1
    const int seg  = ww & 3;          // 0..3
    const int s16  = seg * 16;
    const bool nf = (seg > 0), nl = (seg < 3);

    __shared__ __align__(16) float sIn[6][8][64];   // [rr][ci][w], rr = h0-1+rr
    __shared__ float sWt[8][9][32];                 // [ci][k][co]

    const int fw_co = tid >> 3, fw_ci = tid & 7;

    ull acc[2][8];
#pragma unroll
    for (int r = 0; r < 2; r++)
#pragma unroll
        for (int p = 0; p < 8; p++) acc[r][p] = 0ull;

    for (int cb = 0; cb < 8; cb++) {
        // input fill: 6 rows x 8 ci x 64 = 768 float4/4.. = 768 float4? 3072 floats = 768 f4, 3/thread
#pragma unroll
        for (int t = 0; t < 3; t++) {
            const int i  = tid + t*256;
            const int rr = i >> 7, ci = (i >> 4) & 7, c4 = i & 15;
            const int hh = h0 - 1 + rr;
            float4 v = make_float4(0.f, 0.f, 0.f, 0.f);
            if (hh >= 0 && hh < Hn)
                v = *(const float4*)&g_f1[((b*64 + cb*8 + ci)*Hn + hh)*Wn + c4*4];
            *(float4*)&sIn[rr][ci][c4*4] = v;
        }
        {   // weights: thread = (co32, ci8)
            const float* wp = wgt + (fw_co*64 + cb*8 + fw_ci)*9;
#pragma unroll
            for (int k = 0; k < 9; k++)
                sWt[fw_ci][k][fw_co] = wp[k];
        }
        __syncthreads();

#pragma unroll 2
        for (int ci = 0; ci < 8; ci++) {
            ull A_AP[8], A_S[9], B_AP[8], B_S[9];
            load_row(A_AP, A_S, &sIn[2*rp2 + 0][ci][0], s16, nf, nl);
            load_row(B_AP, B_S, &sIn[2*rp2 + 1][ci][0], s16, nf, nl);
            const float* wr = &sWt[ci][0][lane];
            {
                float v0 = wr[0], v1 = wr[32], v2 = wr[64];
                ull W0 = pack2(v0,v0), W1 = pack2(v1,v1), W2 = pack2(v2,v2);
                fma_row(acc[0], A_AP, A_S, W0, W1, W2);
                fma_row(acc[1], B_AP, B_S, W0, W1, W2);
            }
            load_row(A_AP, A_S, &sIn[2*rp2 + 2][ci][0], s16, nf, nl);
            {
                float v0 = wr[96], v1 = wr[128], v2 = wr[160];
                ull W0 = pack2(v0,v0), W1 = pack2(v1,v1), W2 = pack2(v2,v2);
                fma_row(acc[0], B_AP, B_S, W0, W1, W2);
                fma_row(acc[1], A_AP, A_S, W0, W1, W2);
            }
            load_row(B_AP, B_S, &sIn[2*rp2 + 3][ci][0], s16, nf, nl);
            {
                float v0 = wr[192], v1 = wr[224], v2 = wr[256];
                ull W0 = pack2(v0,v0), W1 = pack2(v1,v1), W2 = pack2(v2,v2);
                fma_row(acc[0], A_AP, A_S, W0, W1, W2);
                fma_row(acc[1], B_AP, B_S, W0, W1, W2);
            }
        }
        __syncthreads();
    }

    const int co = lane;
    const float bv = bias[co], av = alpha[co];
#pragma unroll
    for (int r = 0; r < 2; r++) {
        const int h = h0 + 2*rp2 + r;
#pragma unroll
        for (int p = 0; p < 8; p++) {
            float lo, hi; unpack2(acc[r][p], lo, hi);
            lo += bv; hi += bv;
            lo = lo > 0.f ? lo : av*lo;
            hi = hi > 0.f ? hi : av*hi;
            const int w = s16 + 2*p;
            g_f2t[((b*32 + co)*Wn + w    )*Hn + h] = lo;
            g_f2t[((b*32 + co)*Wn + w + 1)*Hn + h] = hi;
        }
    }
}

// ---------------------------------------------------------------------------
// Fused: 1x1 conv (K=32) + softmax(9) + upsample. 128 thr, 8192 blocks.
// Plain f32 weights: per ci 9 LDS.32 (1 wf each) + dup-pack on ALU.
// Thread = (c_l, pq, pg): 9 logits x 8 h-pixels. out[b][c][2w+q][2h+p].
// ---------------------------------------------------------------------------
__global__ __launch_bounds__(128, 4) void fused_kernel(
    const float* __restrict__ xlow, const float* __restrict__ kw,
    const float* __restrict__ kb, float* __restrict__ out)
{
    const int cchunk = blockIdx.x;
    const int w      = blockIdx.y;
    const int b      = blockIdx.z;
    const int tid = threadIdx.x;
    const int pg  = tid & 7;
    const int pq  = (tid >> 3) & 3;
    const int c_l = tid >> 5;

    __shared__ float swt[144*33];                  // plain f32 weights, pad 33
    __shared__ __align__(16) float sf2[32*64];     // [ci][h]
    __shared__ __align__(16) float sx[4][3][68];   // edge-clamped x_low patch
    __shared__ float sbias[144];

    for (int idx = tid; idx < 32*64; idx += 128)
        sf2[idx] = g_f2t[((b*32 + (idx >> 6))*Wn + w)*Hn + (idx & 63)];
    for (int idx = tid; idx < 144*32; idx += 128) {
        int r = idx >> 5, ci = idx & 31;
        swt[r*33 + ci] = kw[(cchunk*144 + r)*32 + ci];
    }
    for (int idx = tid; idx < 144; idx += 128) sbias[idx] = kb[cchunk*144 + idx];
    for (int idx = tid; idx < 4*3*66; idx += 128) {
        int cl = idx / 198;
        int dx = (idx % 198) / 66;
        int hh = idx % 66;
        int hr = min(max(hh - 1, 0), Hn - 1);
        int wc = min(max(w + dx - 1, 0), Wn - 1);
        sx[cl][dx][hh] = xlow[((b*Cn + cchunk*4 + cl)*Hn + hr)*Wn + wc];
    }
    __syncthreads();

    ull m[9][4];
#pragma unroll
    for (int k = 0; k < 9; k++)
#pragma unroll
        for (int j = 0; j < 4; j++) m[k][j] = 0ull;

    const int rowb = c_l*36 + pq;
    const float* wtb = &swt[rowb*33];

#pragma unroll 4
    for (int ci = 0; ci < 32; ci++) {
        ulonglong2 p01 = *(const ulonglong2*)&sf2[ci*64 + pg*8];
        ulonglong2 p23 = *(const ulonglong2*)&sf2[ci*64 + pg*8 + 4];
        ull P[4] = {p01.x, p01.y, p23.x, p23.y};
        ull W[9];
#pragma unroll
        for (int k = 0; k < 9; k++) {
            float v = wtb[k*132 + ci];   // 132 = 4*33 (rows step by 4)
            W[k] = pack2(v, v);
        }
#pragma unroll
        for (int k = 0; k < 9; k++)
#pragma unroll
            for (int j = 0; j < 4; j++) m[k][j] = ffma2(W[k], P[j], m[k][j]);
    }

    float b9[9];
#pragma unroll
    for (int k = 0; k < 9; k++) b9[k] = sbias[rowb + k*4];

    float nbd[3][10];
#pragma unroll
    for (int dx = 0; dx < 3; dx++) {
        float4 q0 = *(const float4*)&sx[c_l][dx][pg*8];
        float4 q1 = *(const float4*)&sx[c_l][dx][pg*8 + 4];
        float2 q2 = *(const float2*)&sx[c_l][dx][pg*8 + 8];
        nbd[dx][0]=q0.x; nbd[dx][1]=q0.y; nbd[dx][2]=q0.z; nbd[dx][3]=q0.w;
        nbd[dx][4]=q1.x; nbd[dx][5]=q1.y; nbd[dx][6]=q1.z; nbd[dx][7]=q1.w;
        nbd[dx][8]=q2.x; nbd[dx][9]=q2.y;
    }

    const int c = cchunk*4 + c_l;
    const int p = pq >> 1, q = pq & 1;
    float* orow = &out[((b*Cn + c)*128 + (2*w + q))*128 + p];

#pragma unroll
    for (int jj = 0; jj < 4; jj++) {
        float lo[9], hi[9];
#pragma unroll
        for (int k = 0; k < 9; k++) unpack2(m[k][jj], lo[k], hi[k]);
#pragma unroll
        for (int e = 0; e < 2; e++) {
            const int j = 2*jj + e;
            const float* lv = e ? hi : lo;
            float se = 0.f, sv = 0.f;
#pragma unroll
            for (int k = 0; k < 9; k++) {
                float ex = __expf(lv[k] + b9[k]);   // logits tiny: no max-sub needed
                se += ex;
                sv = fmaf(ex, nbd[k % 3][j + k / 3], sv);
            }
            orow[2*(pg*8 + j)] = sv * __fdividef(1.f, se);
        }
    }
}

extern "C" void kernel_launch(void* const* d_in, const int* in_sizes, int n_in,
                              void* d_out, int out_size)
{
    const float* x_low = (const float*)d_in[0];
    const float* ctx   = (const float*)d_in[1];
    const float* c1_w  = (const float*)d_in[2];
    const float* c1_b  = (const float*)d_in[3];
    const float* p1_a  = (const float*)d_in[4];
    const float* c2_w  = (const float*)d_in[5];
    const float* c2_b  = (const float*)d_in[6];
    const float* p2_a  = (const float*)d_in[7];
    const float* kp_w  = (const float*)d_in[8];
    const float* kp_b  = (const float*)d_in[9];
    float* out = (float*)d_out;

    conv1_kernel<<<dim3(32, 8), 256>>>(ctx, c1_w, c1_b, p1_a);
    conv2_kernel<<<dim3(16, 8), 256>>>(c2_w, c2_b, p2_a);
    fused_kernel<<<dim3(16, Wn, Bn), 128>>>(x_low, kp_w, kp_b, out);
}